// round 16
// baseline (speedup 1.0000x reference)
#include <cuda_runtime.h>

#define N_PARTICLES_MAX 262144

__device__ float4 g_x4[N_PARTICLES_MAX];
__device__ double g_sum = 0.0;
__device__ unsigned int g_count = 0u;
__device__ unsigned int g_bar = 0u;      // monotonic grid barrier (never reset)

// Fused persistent kernel: phase 1 repacks x into float4, grid barrier,
// phase 2 does the pair sum (record inner loop). Single wave guaranteed by
// the host launching exactly occupancy*SMs blocks.
__global__ void __launch_bounds__(256) lj_fused(
        const float* __restrict__ x, int n_particles,
        const int4* __restrict__ idx_i4,
        const int4* __restrict__ idx_j4,
        const float* __restrict__ eps_p,
        const float* __restrict__ sigma_p,
        const float* __restrict__ box_p,
        int n4,
        float* __restrict__ out) {
    int t = blockIdx.x * blockDim.x + threadIdx.x;
    int stride = gridDim.x * blockDim.x;

    // ---- phase 1: repack (coalesced; ~1 particle per thread) ----
    for (int p = t; p < n_particles; p += stride) {
        float a = x[3 * p + 0];
        float b = x[3 * p + 1];
        float c = x[3 * p + 2];
        g_x4[p] = make_float4(a, b, c, 0.0f);
    }
    __threadfence();
    __syncthreads();

    // ---- grid barrier (monotonic; replay-safe) ----
    if (threadIdx.x == 0) {
        unsigned int my = atomicAdd(&g_bar, 1u) + 1u;
        unsigned int target = ((my - 1u) / gridDim.x + 1u) * gridDim.x;
        while (atomicAdd(&g_bar, 0u) < target) __nanosleep(64);
    }
    __syncthreads();

    // ---- phase 2: pair energies (record inner loop) ----
    const float L = box_p[0];
    const float invL = 1.0f / L;
    const float sigma = sigma_p[0];
    const float sigma2 = sigma * sigma;

    float acc = 0.0f;

    for (int v = t; v < n4; v += stride) {
        int4 iv = idx_i4[v];
        int4 jv = idx_j4[v];
        int is[4] = {iv.x, iv.y, iv.z, iv.w};
        int js[4] = {jv.x, jv.y, jv.z, jv.w};
#pragma unroll
        for (int k = 0; k < 4; k++) {
            float4 pi = __ldg(&g_x4[is[k]]);
            float4 pj = __ldg(&g_x4[js[k]]);
            float dx = pi.x - pj.x;
            float dy = pi.y - pj.y;
            float dz = pi.z - pj.z;
            dx -= L * rintf(dx * invL);
            dy -= L * rintf(dy * invL);
            dz -= L * rintf(dz * invL);
            float r2 = fmaf(dx, dx, fmaf(dy, dy, dz * dz));
            float s2 = sigma2 / r2;
            float s6 = s2 * s2 * s2;
            acc += fmaf(s6, s6, -s6);   // s12 - s6
        }
    }

    acc *= 4.0f * eps_p[0];

    // warp reduce (float), then block reduce in double, one atomic per block
    for (int off = 16; off > 0; off >>= 1)
        acc += __shfl_down_sync(0xFFFFFFFFu, acc, off);

    __shared__ double warp_sums[8];
    int lane = threadIdx.x & 31;
    int wid  = threadIdx.x >> 5;
    if (lane == 0) warp_sums[wid] = (double)acc;
    __syncthreads();

    if (wid == 0) {
        double s = (lane < 8) ? warp_sums[lane] : 0.0;
        for (int off = 4; off > 0; off >>= 1)
            s += __shfl_down_sync(0xFFFFFFFFu, s, off);
        if (lane == 0) {
            atomicAdd(&g_sum, s);
            __threadfence();
            unsigned int ticket = atomicAdd(&g_count, 1u) + 1u;
            if (ticket % gridDim.x == 0u) {
                // last block of THIS launch: publish and reset for next replay
                out[0] = (float)g_sum;
                g_sum = 0.0;
            }
        }
    }
}

extern "C" void kernel_launch(void* const* d_in, const int* in_sizes, int n_in,
                              void* d_out, int out_size) {
    const float* x       = (const float*)d_in[0];   // [N,3]
    const float* eps_p   = (const float*)d_in[1];   // scalar
    const float* sigma_p = (const float*)d_in[2];   // scalar
    const float* box_p   = (const float*)d_in[3];   // [3]
    const int*   idx_i   = (const int*)d_in[4];     // [n_pairs]
    const int*   idx_j   = (const int*)d_in[5];     // [n_pairs]

    int n_particles = in_sizes[0] / 3;
    int n_pairs     = in_sizes[4];
    int n4          = n_pairs / 4;       // 2M quads of 4 pairs

    // Exactly one wave: occupancy * SM count (deadlock-free by construction).
    int threads = 256;
    static int blocks = 0;               // deterministic; computed once
    if (blocks == 0) {
        int per_sm = 0, sms = 0;
        cudaOccupancyMaxActiveBlocksPerMultiprocessor(&per_sm, lj_fused,
                                                      threads, 0);
        cudaDeviceGetAttribute(&sms, cudaDevAttrMultiProcessorCount, 0);
        if (per_sm < 1) per_sm = 1;
        if (sms < 1) sms = 148;
        blocks = per_sm * sms;
        int max_blocks = (n4 + threads - 1) / threads;
        if (blocks > max_blocks) blocks = max_blocks;
    }

    lj_fused<<<blocks, threads>>>(x, n_particles,
                                  (const int4*)idx_i, (const int4*)idx_j,
                                  eps_p, sigma_p, box_p, n4,
                                  (float*)d_out);
}

// round 17
// speedup vs baseline: 1.0242x; 1.0242x over previous
#include <cuda_runtime.h>

#define N_PARTICLES_MAX 262144

__device__ float4 g_x4[N_PARTICLES_MAX];
__device__ double g_sum;
__device__ unsigned int g_count;

// Repack x [N,3] -> float4 (16B-aligned), zero accumulator + ticket counter.
// Triggers programmatic launch of the main kernel immediately so the main
// kernel's launch latency overlaps this kernel's execution.
__global__ void repack_kernel(const float* __restrict__ x, int n) {
    cudaTriggerProgrammaticLaunchCompletion();
    int p = blockIdx.x * blockDim.x + threadIdx.x;
    if (p == 0) { g_sum = 0.0; g_count = 0u; }
    if (p < n) {
        float a = x[3 * p + 0];
        float b = x[3 * p + 1];
        float c = x[3 * p + 2];
        g_x4[p] = make_float4(a, b, c, 0.0f);
    }
}

// Persistent main kernel: one wave, grid-stride over all quads.
// PDL: launches while repack is still running; syncs on full repack
// completion just before the first gather. Last block writes the result.
__global__ void lj_kernel(const int4* __restrict__ idx_i4,
                          const int4* __restrict__ idx_j4,
                          const float* __restrict__ eps_p,
                          const float* __restrict__ sigma_p,
                          const float* __restrict__ box_p,
                          int n4,
                          float* __restrict__ out) {
    // Pre-sync work: scalars not written by repack.
    const float L = box_p[0];
    const float invL = 1.0f / L;
    const float sigma = sigma_p[0];
    const float sigma2 = sigma * sigma;
    const float eps4 = 4.0f * eps_p[0];

    int t = blockIdx.x * blockDim.x + threadIdx.x;
    int stride = gridDim.x * blockDim.x;

    // Wait for repack to fully complete (memory-visibility guaranteed).
    cudaGridDependencySynchronize();

    float acc = 0.0f;

    for (int v = t; v < n4; v += stride) {
        int4 iv = idx_i4[v];
        int4 jv = idx_j4[v];
        int is[4] = {iv.x, iv.y, iv.z, iv.w};
        int js[4] = {jv.x, jv.y, jv.z, jv.w};
#pragma unroll
        for (int k = 0; k < 4; k++) {
            float4 pi = __ldg(&g_x4[is[k]]);
            float4 pj = __ldg(&g_x4[js[k]]);
            float dx = pi.x - pj.x;
            float dy = pi.y - pj.y;
            float dz = pi.z - pj.z;
            dx -= L * rintf(dx * invL);
            dy -= L * rintf(dy * invL);
            dz -= L * rintf(dz * invL);
            float r2 = fmaf(dx, dx, fmaf(dy, dy, dz * dz));
            float s2 = sigma2 / r2;
            float s6 = s2 * s2 * s2;
            acc += fmaf(s6, s6, -s6);   // s12 - s6
        }
    }

    acc *= eps4;

    // warp reduce (float), then block reduce in double, one atomic per block
    for (int off = 16; off > 0; off >>= 1)
        acc += __shfl_down_sync(0xFFFFFFFFu, acc, off);

    __shared__ double warp_sums[8];
    int lane = threadIdx.x & 31;
    int wid  = threadIdx.x >> 5;
    if (lane == 0) warp_sums[wid] = (double)acc;
    __syncthreads();

    if (wid == 0) {
        double s = (lane < 8) ? warp_sums[lane] : 0.0;
        for (int off = 4; off > 0; off >>= 1)
            s += __shfl_down_sync(0xFFFFFFFFu, s, off);
        if (lane == 0) {
            atomicAdd(&g_sum, s);
            __threadfence();
            unsigned int ticket = atomicAdd(&g_count, 1u);
            if (ticket == gridDim.x - 1) {
                out[0] = (float)g_sum;
            }
        }
    }
}

extern "C" void kernel_launch(void* const* d_in, const int* in_sizes, int n_in,
                              void* d_out, int out_size) {
    const float* x       = (const float*)d_in[0];   // [N,3]
    const float* eps_p   = (const float*)d_in[1];   // scalar
    const float* sigma_p = (const float*)d_in[2];   // scalar
    const float* box_p   = (const float*)d_in[3];   // [3]
    const int*   idx_i   = (const int*)d_in[4];     // [n_pairs]
    const int*   idx_j   = (const int*)d_in[5];     // [n_pairs]

    int n_particles = in_sizes[0] / 3;
    int n_pairs     = in_sizes[4];
    int n4          = n_pairs / 4;       // 2M quads of 4 pairs

    // One-wave grid for the persistent main kernel.
    int threads = 256;
    static int blocks = 0;               // deterministic; computed once
    if (blocks == 0) {
        int per_sm = 0, sms = 0;
        cudaOccupancyMaxActiveBlocksPerMultiprocessor(&per_sm, lj_kernel,
                                                      threads, 0);
        cudaDeviceGetAttribute(&sms, cudaDevAttrMultiProcessorCount, 0);
        if (per_sm < 1) per_sm = 1;
        if (sms < 1) sms = 148;
        blocks = per_sm * sms;
        int max_blocks = (n4 + threads - 1) / threads;
        if (blocks > max_blocks) blocks = max_blocks;
    }

    // 1) repack (triggers programmatic completion at entry)
    {
        int rthreads = 128;
        int rblocks = (n_particles + rthreads - 1) / rthreads;  // 2048
        repack_kernel<<<rblocks, rthreads>>>(x, n_particles);
    }

    // 2) main pair kernel with Programmatic Dependent Launch
    {
        cudaLaunchConfig_t cfg = {};
        cfg.gridDim  = dim3((unsigned)blocks, 1, 1);
        cfg.blockDim = dim3((unsigned)threads, 1, 1);
        cfg.dynamicSmemBytes = 0;
        cfg.stream = 0;
        cudaLaunchAttribute attrs[1];
        attrs[0].id = cudaLaunchAttributeProgrammaticStreamSerialization;
        attrs[0].val.programmaticStreamSerializationAllowed = 1;
        cfg.attrs = attrs;
        cfg.numAttrs = 1;
        cudaLaunchKernelEx(&cfg, lj_kernel,
                           (const int4*)idx_i, (const int4*)idx_j,
                           eps_p, sigma_p, box_p, n4, (float*)d_out);
    }
}